// round 13
// baseline (speedup 1.0000x reference)
#include <cuda_runtime.h>
#include <cuda_fp16.h>
#include <cstdint>

#define BB 2
#define NN 2048
#define DD 1024
#define HH 16
#define DH 64
#define MM (BB*NN)
#define SMP 72   // smem pitch in halves (144B rows, 16B-aligned, ldsm conflict-free)

// ---------------- scratch (__device__ globals) -----------------------------
__device__ __half g_xh[(size_t)MM*DD];
__device__ __half g_wq[(size_t)DD*DD];
__device__ __half g_wk[(size_t)DD*DD];
__device__ __half g_wv[(size_t)DD*DD];
__device__ __half g_wo[(size_t)DD*DD];
__device__ __half g_bh[(size_t)BB*NN*NN];  // fp16 attn bias (unshifted)
__device__ __half g_qh[(size_t)MM*DD];     // head-major (b,h,n,dh)
__device__ __half g_kh[(size_t)MM*DD];
__device__ __half g_vh[(size_t)MM*DD];
__device__ __half g_ao[(size_t)MM*DD];     // row-major (b,n,D) fp16

// ---------------- helpers ---------------------------------------------------
__device__ __forceinline__ uint32_t s2u(const void* p) {
    uint32_t a;
    asm("{ .reg .u64 t; cvta.to.shared.u64 t, %1; cvt.u32.u64 %0, t; }" : "=r"(a) : "l"(p));
    return a;
}
__device__ __forceinline__ void ldsm4(uint32_t* r, uint32_t a) {
    asm volatile("ldmatrix.sync.aligned.m8n8.x4.shared.b16 {%0,%1,%2,%3}, [%4];"
                 : "=r"(r[0]), "=r"(r[1]), "=r"(r[2]), "=r"(r[3]) : "r"(a));
}
__device__ __forceinline__ void ldsm4t(uint32_t* r, uint32_t a) {
    asm volatile("ldmatrix.sync.aligned.m8n8.x4.trans.shared.b16 {%0,%1,%2,%3}, [%4];"
                 : "=r"(r[0]), "=r"(r[1]), "=r"(r[2]), "=r"(r[3]) : "r"(a));
}
__device__ __forceinline__ void mma16816(float* c, const uint32_t* a, const uint32_t* b) {
    asm volatile(
        "mma.sync.aligned.m16n8k16.row.col.f32.f16.f16.f32 "
        "{%0,%1,%2,%3}, {%4,%5,%6,%7}, {%8,%9}, {%0,%1,%2,%3};"
        : "+f"(c[0]), "+f"(c[1]), "+f"(c[2]), "+f"(c[3])
        : "r"(a[0]), "r"(a[1]), "r"(a[2]), "r"(a[3]), "r"(b[0]), "r"(b[1]));
}
__device__ __forceinline__ uint32_t packh2(float x, float y) {
    __half2 h = __floats2half2_rn(x, y);
    return *(uint32_t*)&h;
}
__device__ __forceinline__ void cpa16(uint32_t dst, const void* src) {
    asm volatile("cp.async.cg.shared.global [%0], [%1], 16;" :: "r"(dst), "l"(src));
}
#define CP_COMMIT() asm volatile("cp.async.commit_group;" ::: "memory")
#define CP_WAIT(n)  asm volatile("cp.async.wait_group %0;" :: "n"(n) : "memory")

// ---------------- fp32 -> fp16 converts --------------------------------------
__global__ void conv_f2h(const float* __restrict__ in, __half* __restrict__ out) {
    size_t i = (size_t)blockIdx.x * blockDim.x + threadIdx.x;
    float4 v = ((const float4*)in)[i];
    __half2* o = (__half2*)out;
    o[2*i]   = __floats2half2_rn(v.x, v.y);
    o[2*i+1] = __floats2half2_rn(v.z, v.w);
}
__global__ void conv_w4(const float* __restrict__ w0, const float* __restrict__ w1,
                        const float* __restrict__ w2, const float* __restrict__ w3,
                        __half* __restrict__ o0, __half* __restrict__ o1,
                        __half* __restrict__ o2, __half* __restrict__ o3) {
    const int z = blockIdx.y;
    const float* in = (z == 0) ? w0 : (z == 1) ? w1 : (z == 2) ? w2 : w3;
    __half* out     = (z == 0) ? o0 : (z == 1) ? o1 : (z == 2) ? o2 : o3;
    size_t i = (size_t)blockIdx.x * blockDim.x + threadIdx.x;
    float4 v = ((const float4*)in)[i];
    __half2* o = (__half2*)out;
    o[2*i]   = __floats2half2_rn(v.x, v.y);
    o[2*i+1] = __floats2half2_rn(v.z, v.w);
}

// ---------------- shared GEMM mainloop: 3-stage, single barrier per chunk ---
// 128x128 block, 256 threads, k-chunks of 64.
// smem: stage s at base + s*36864 (A) / +18432 (B), s = 0,1,2.  110592 B.
#define GEMM_MAINLOOP(A_, W_)                                                  \
    const int tid = threadIdx.x, lane = tid & 31, wid = tid >> 5;              \
    const int wm = wid >> 2, wn = wid & 3;                                     \
    const int g = lane >> 2, t4 = lane & 3;                                    \
    const int m0 = blockIdx.x * 128, e0 = blockIdx.y * 128;                    \
    const int lrow = tid >> 1, lseg = tid & 1;                                 \
    const uint32_t base = s2u(dsm);                                            \
    const uint32_t rowoff = (uint32_t)lrow * 144u + (uint32_t)lseg * 64u;      \
    const __half* ga = A_ + (size_t)(m0 + lrow) * DD + lseg * 32;              \
    const __half* gw = W_ + (size_t)(e0 + lrow) * DD + lseg * 32;              \
    _Pragma("unroll")                                                          \
    for (int j = 0; j < 4; j++) cpa16(base + rowoff + j*16, ga + j*8);         \
    _Pragma("unroll")                                                          \
    for (int j = 0; j < 4; j++) cpa16(base + 18432 + rowoff + j*16, gw + j*8); \
    CP_COMMIT();                                                               \
    _Pragma("unroll")                                                          \
    for (int j = 0; j < 4; j++) cpa16(base + 36864 + rowoff + j*16, ga + 64 + j*8); \
    _Pragma("unroll")                                                          \
    for (int j = 0; j < 4; j++) cpa16(base + 55296 + rowoff + j*16, gw + 64 + j*8); \
    CP_COMMIT();                                                               \
    float acc[4][4][4] = {};                                                   \
    uint32_t rdA = base;                                                       \
    uint32_t wrA = base + 2*36864u;                                            \
    for (int c = 0; c < 16; c++) {                                             \
        if (c < 15) { CP_WAIT(1); } else { CP_WAIT(0); }                       \
        __syncthreads();                                                       \
        if (c + 2 < 16) {                                                      \
            const __half* sa = ga + (c + 2) * 64;                              \
            const __half* sw = gw + (c + 2) * 64;                              \
            _Pragma("unroll")                                                  \
            for (int j = 0; j < 4; j++) cpa16(wrA + rowoff + j*16, sa + j*8);  \
            _Pragma("unroll")                                                  \
            for (int j = 0; j < 4; j++) cpa16(wrA + 18432 + rowoff + j*16, sw + j*8); \
            CP_COMMIT();                                                       \
        }                                                                      \
        const uint32_t aB = rdA, bB = rdA + 18432u;                            \
        _Pragma("unroll")                                                      \
        for (int ks = 0; ks < 4; ks++) {                                       \
            uint32_t af[4][4];                                                 \
            _Pragma("unroll")                                                  \
            for (int mt = 0; mt < 4; mt++)                                     \
                ldsm4(af[mt], aB + ((wm*64 + mt*16 + (lane & 15)) * SMP        \
                                    + ks*16 + ((lane >> 4) << 3)) * 2);        \
            uint32_t bf[2][4];                                                 \
            _Pragma("unroll")                                                  \
            for (int np = 0; np < 2; np++)                                     \
                ldsm4(bf[np], bB + ((wn*32 + np*16 + ((lane >> 4) << 3)        \
                                    + (lane & 7)) * SMP                        \
                                    + ks*16 + (((lane >> 3) & 1) << 3)) * 2);  \
            _Pragma("unroll")                                                  \
            for (int mt = 0; mt < 4; mt++)                                     \
                _Pragma("unroll")                                              \
                for (int nt = 0; nt < 4; nt++)                                 \
                    mma16816(acc[mt][nt], af[mt], &bf[nt >> 1][(nt & 1) * 2]); \
        }                                                                      \
        wrA = rdA;                                                             \
        rdA = (rdA == base + 2*36864u) ? base : rdA + 36864u;                  \
    }                                                                          \
    __syncthreads();

// ---------------- fused QKV projection + LN (Q,K) ---------------------------
__global__ void __launch_bounds__(256) gemm_qkv(
    const __half* __restrict__ A,
    const __half* __restrict__ Wqp, const __half* __restrict__ Wkp, const __half* __restrict__ Wvp,
    const float* __restrict__ bqp, const float* __restrict__ bkp, const float* __restrict__ bvp,
    const float* __restrict__ qgp, const float* __restrict__ qbp,
    const float* __restrict__ kgp, const float* __restrict__ kbp,
    __half* __restrict__ qhp, __half* __restrict__ khp, __half* __restrict__ vhp)
{
    extern __shared__ char dsm[];
    const int z = blockIdx.z;
    const __half* W   = (z == 0) ? Wqp : (z == 1) ? Wkp : Wvp;
    const float* bias = (z == 0) ? bqp : (z == 1) ? bkp : bvp;

    GEMM_MAINLOOP(A, W)

    if (z == 2) {
        #pragma unroll
        for (int mt = 0; mt < 4; mt++) {
            #pragma unroll
            for (int nt = 0; nt < 4; nt++) {
                int m = m0 + wm*64 + mt*16 + g;
                int e = e0 + wn*32 + nt*8 + 2*t4;
                float b0 = bias[e], b1 = bias[e + 1];
                int hh = e >> 6, hd = e & 63;
                int b_ = m >> 11, n = m & 2047;
                *(__half2*)(vhp + (((size_t)b_*HH + hh)*NN + n)     * DH + hd) =
                    __floats2half2_rn(acc[mt][nt][0] + b0, acc[mt][nt][1] + b1);
                *(__half2*)(vhp + (((size_t)b_*HH + hh)*NN + n + 8) * DH + hd) =
                    __floats2half2_rn(acc[mt][nt][2] + b0, acc[mt][nt][3] + b1);
            }
        }
    } else {
        float* stage = (float*)dsm;
        #pragma unroll
        for (int mt = 0; mt < 4; mt++) {
            #pragma unroll
            for (int nt = 0; nt < 4; nt++) {
                int r = wm*64 + mt*16 + g;
                int e = wn*32 + nt*8 + 2*t4;
                float b0 = bias[e0 + e], b1 = bias[e0 + e + 1];
                *(float2*)&stage[r*132 + e] =
                    make_float2(acc[mt][nt][0] + b0, acc[mt][nt][1] + b1);
                *(float2*)&stage[(r + 8)*132 + e] =
                    make_float2(acc[mt][nt][2] + b0, acc[mt][nt][3] + b1);
            }
        }
        __syncthreads();
        const float* gam = z ? kgp : qgp;
        const float* bet = z ? kbp : qbp;
        __half* outp = z ? khp : qhp;
        float gm0 = gam[lane], gm1 = gam[lane + 32];
        float bt0 = bet[lane], bt1 = bet[lane + 32];
        #pragma unroll 4
        for (int t = 0; t < 32; t++) {
            int task = t*8 + wid;
            int r = task >> 1, hh = task & 1;
            float v0 = stage[r*132 + hh*64 + lane];
            float v1 = stage[r*132 + hh*64 + lane + 32];
            float s = v0 + v1;
            #pragma unroll
            for (int o = 16; o > 0; o >>= 1) s += __shfl_xor_sync(0xffffffffu, s, o);
            float mu = s * (1.0f / 64.0f);
            float d0 = v0 - mu, d1 = v1 - mu;
            float vs = d0*d0 + d1*d1;
            #pragma unroll
            for (int o = 16; o > 0; o >>= 1) vs += __shfl_xor_sync(0xffffffffu, vs, o);
            float rs = rsqrtf(vs * (1.0f / 64.0f) + 1e-6f);
            int m = m0 + r, b_ = m >> 11, n = m & 2047;
            int hglob = (e0 >> 6) + hh;
            __half* dst = outp + (((size_t)b_*HH + hglob)*NN + n) * DH;
            dst[lane]      = __float2half_rn(d0 * rs * gm0 + bt0);
            dst[lane + 32] = __float2half_rn(d1 * rs * gm1 + bt1);
        }
    }
}

// ---------------- output projection (fp32 row-major out) --------------------
__global__ void __launch_bounds__(256) gemm_out(
    const __half* __restrict__ A, const __half* __restrict__ W,
    const float* __restrict__ bias, float* __restrict__ outf)
{
    extern __shared__ char dsm[];
    GEMM_MAINLOOP(A, W)
    #pragma unroll
    for (int mt = 0; mt < 4; mt++) {
        #pragma unroll
        for (int nt = 0; nt < 4; nt++) {
            int m = m0 + wm*64 + mt*16 + g;
            int e = e0 + wn*32 + nt*8 + 2*t4;
            float b0 = bias[e], b1 = bias[e + 1];
            *(float2*)(outf + (size_t)m * DD + e) =
                make_float2(acc[mt][nt][0] + b0, acc[mt][nt][1] + b1);
            *(float2*)(outf + (size_t)(m + 8) * DD + e) =
                make_float2(acc[mt][nt][2] + b0, acc[mt][nt][3] + b1);
        }
    }
}

// ---------------- attention: fused QK->exp->PV per 16-key group -------------
// 128 thr, 64q tile, 64k chunks, bias in smem (unshifted fp16).
// smem bytes: Q@0 | K0@9216 | V0@18432 | B0@27648 | K1@36864 | V1@46080 | B1@55296
__global__ void __launch_bounds__(128, 3) attn_hmma(const __half* __restrict__ q,
                                                    const __half* __restrict__ k,
                                                    const __half* __restrict__ v,
                                                    const __half* __restrict__ bias16,
                                                    __half* __restrict__ out)
{
    extern __shared__ __half sm[];
    const int tid = threadIdx.x, lane = tid & 31, wid = tid >> 5;
    const int g = lane >> 2, t4 = lane & 3;
    const int qt = blockIdx.x, h = blockIdx.y, b = blockIdx.z;
    const int lrow = tid >> 1, lseg = tid & 1;   // 64 rows x 2 segments

    const __half* qp = q + (((size_t)b*HH + h)*NN + qt*64) * DH;
    const __half* kp = k + ((size_t)b*HH + h)*NN * DH;
    const __half* vp = v + ((size_t)b*HH + h)*NN * DH;
    const __half* gb = bias16 + ((size_t)b*NN + qt*64 + lrow) * NN + lseg * 32;

    const uint32_t base = s2u(sm);
    const uint32_t qS = base;
    const uint32_t kS0 = base + 9216,  vS0 = base + 18432, bS0 = base + 27648;
    const uint32_t kS1 = base + 36864, vS1 = base + 46080, bS1 = base + 55296;
    const uint32_t rowoff = (uint32_t)lrow * 144u + (uint32_t)lseg * 64u;

    // stage Q + prefetch chunk 0 (K, V, bias)
    {
        const __half* qs = qp + (size_t)lrow * DH + lseg * 32;
        const __half* ks = kp + (size_t)lrow * DH + lseg * 32;
        const __half* vs = vp + (size_t)lrow * DH + lseg * 32;
        #pragma unroll
        for (int j = 0; j < 4; j++) cpa16(qS  + rowoff + j*16, qs + j*8);
        #pragma unroll
        for (int j = 0; j < 4; j++) cpa16(kS0 + rowoff + j*16, ks + j*8);
        #pragma unroll
        for (int j = 0; j < 4; j++) cpa16(vS0 + rowoff + j*16, vs + j*8);
        #pragma unroll
        for (int j = 0; j < 4; j++) cpa16(bS0 + rowoff + j*16, gb + j*8);
        CP_COMMIT();
    }
    CP_WAIT(0);
    __syncthreads();

    uint32_t qf[4][4];
    #pragma unroll
    for (int ks = 0; ks < 4; ks++)
        ldsm4(qf[ks], qS + ((wid*16 + (lane & 15)) * SMP
                            + ks*16 + ((lane >> 4) << 3)) * 2);

    float o[8][4] = {};
    float l0 = 0.0f, l1 = 0.0f;
    const int r0 = wid * 16 + g;                 // local query row (first 8-group)

    for (int c = 0; c < 32; c++) {               // 32 chunks of 64 keys
        if (c + 1 < 32) {
            const uint32_t dk = ((c + 1) & 1) ? kS1 : kS0;
            const uint32_t dv = ((c + 1) & 1) ? vS1 : vS0;
            const uint32_t db = ((c + 1) & 1) ? bS1 : bS0;
            const __half* ks = kp + ((size_t)(c + 1)*64 + lrow) * DH + lseg * 32;
            const __half* vs = vp + ((size_t)(c + 1)*64 + lrow) * DH + lseg * 32;
            const __half* bs = gb + (c + 1) * 64;
            #pragma unroll
            for (int j = 0; j < 4; j++) cpa16(dk + rowoff + j*16, ks + j*8);
            #pragma unroll
            for (int j = 0; j < 4; j++) cpa16(dv + rowoff + j*16, vs + j*8);
            #pragma unroll
            for (int j = 0; j < 4; j++) cpa16(db + rowoff + j*16, bs + j*8);
            CP_COMMIT();
            CP_WAIT(1);
        } else {
            CP_WAIT(0);
        }
        __syncthreads();
        const uint32_t kB = (c & 1) ? kS1 : kS0;
        const uint32_t vB = (c & 1) ? vS1 : vS0;
        const __half* bsm = sm + ((c & 1) ? 27648 : 13824);   // half-index of bias buf

        #pragma unroll
        for (int np = 0; np < 4; np++) {         // 4 groups of 16 keys, fused
            float s[2][4] = {};
            #pragma unroll
            for (int ks = 0; ks < 4; ks++) {
                uint32_t bfr[4];
                ldsm4(bfr, kB + ((np*16 + ((lane >> 4) << 3) + (lane & 7)) * SMP
                                 + ks*16 + (((lane >> 3) & 1) << 3)) * 2);
                mma16816(s[0], qf[ks], bfr);
                mma16816(s[1], qf[ks], bfr + 2);
            }
            uint32_t a[4];
            #pragma unroll
            for (int e = 0; e < 2; e++) {
                int col = (2*np + e)*8 + 2*t4;   // local key col
                float2 bb0 = __half22float2(*(const __half2*)(bsm + r0*SMP + col));
                float2 bb1 = __half22float2(*(const __half2*)(bsm + (r0 + 8)*SMP + col));
                float p0 = __expf(fmaf(s[e][0], 0.125f, bb0.x) - 6.0f);
                float p1 = __expf(fmaf(s[e][1], 0.125f, bb0.y) - 6.0f);
                float p2 = __expf(fmaf(s[e][2], 0.125f, bb1.x) - 6.0f);
                float p3 = __expf(fmaf(s[e][3], 0.125f, bb1.y) - 6.0f);
                l0 += p0 + p1;
                l1 += p2 + p3;
                a[2*e]     = packh2(p0, p1);
                a[2*e + 1] = packh2(p2, p3);
            }
            #pragma unroll
            for (int dp = 0; dp < 4; dp++) {
                uint32_t bfr[4];
                ldsm4t(bfr, vB + ((np*16 + (lane & 15)) * SMP
                                  + dp*16 + ((lane >> 4) << 3)) * 2);
                mma16816(o[2*dp],     a, bfr);
                mma16816(o[2*dp + 1], a, bfr + 2);
            }
        }
        __syncthreads();
    }

    l0 += __shfl_xor_sync(0xffffffffu, l0, 1);
    l0 += __shfl_xor_sync(0xffffffffu, l0, 2);
    l1 += __shfl_xor_sync(0xffffffffu, l1, 1);
    l1 += __shfl_xor_sync(0xffffffffu, l1, 2);
    float inv0 = 1.0f / l0, inv1 = 1.0f / l1;

    __half* or0 = out + ((size_t)b*NN + qt*64 + wid*16 + g) * DD + h * DH;
    __half* or1 = or0 + 8 * DD;
    #pragma unroll
    for (int dt = 0; dt < 8; dt++) {
        int d = dt*8 + 2*t4;
        *(__half2*)(or0 + d) = __floats2half2_rn(o[dt][0] * inv0, o[dt][1] * inv0);
        *(__half2*)(or1 + d) = __floats2half2_rn(o[dt][2] * inv1, o[dt][3] * inv1);
    }
}

// ---------------------------------------------------------------------------
extern "C" void kernel_launch(void* const* d_in, const int* in_sizes, int n_in,
                              void* d_out, int out_size)
{
    const float* x  = (const float*)d_in[0];
    const float* ab = (const float*)d_in[1];
    const float* Wq = (const float*)d_in[2];
    const float* bq = (const float*)d_in[3];
    const float* Wk = (const float*)d_in[4];
    const float* bk = (const float*)d_in[5];
    const float* Wv = (const float*)d_in[6];
    const float* bv = (const float*)d_in[7];
    const float* Wo = (const float*)d_in[8];
    const float* bo = (const float*)d_in[9];
    const float* qg = (const float*)d_in[10];
    const float* qb = (const float*)d_in[11];
    const float* kg = (const float*)d_in[12];
    const float* kb = (const float*)d_in[13];
    float* out = (float*)d_out;

    __half *xh, *wq, *wk, *wv, *wo, *bh, *qh, *kh, *vh, *ao;
    cudaGetSymbolAddress((void**)&xh, g_xh);
    cudaGetSymbolAddress((void**)&wq, g_wq);
    cudaGetSymbolAddress((void**)&wk, g_wk);
    cudaGetSymbolAddress((void**)&wv, g_wv);
    cudaGetSymbolAddress((void**)&wo, g_wo);
    cudaGetSymbolAddress((void**)&bh, g_bh);
    cudaGetSymbolAddress((void**)&qh, g_qh);
    cudaGetSymbolAddress((void**)&kh, g_kh);
    cudaGetSymbolAddress((void**)&vh, g_vh);
    cudaGetSymbolAddress((void**)&ao, g_ao);

    const int GEMM_SMEM = 110592;
    const int ATTN_SMEM = 64512;
    cudaFuncSetAttribute(gemm_qkv,  cudaFuncAttributeMaxDynamicSharedMemorySize, GEMM_SMEM);
    cudaFuncSetAttribute(gemm_out,  cudaFuncAttributeMaxDynamicSharedMemorySize, GEMM_SMEM);
    cudaFuncSetAttribute(attn_hmma, cudaFuncAttributeMaxDynamicSharedMemorySize, ATTN_SMEM);

    conv_f2h<<<(MM*DD)/1024, 256>>>(x, xh);
    conv_f2h<<<(BB*NN*NN)/1024, 256>>>(ab, bh);
    conv_w4<<<dim3((DD*DD)/1024, 4), 256>>>(Wq, Wk, Wv, Wo, wq, wk, wv, wo);

    gemm_qkv<<<dim3(MM/128, DD/128, 3), 256, GEMM_SMEM>>>(
        xh, wq, wk, wv, bq, bk, bv, qg, qb, kg, kb, qh, kh, vh);

    attn_hmma<<<dim3(NN/64, HH, BB), 128, ATTN_SMEM>>>(qh, kh, vh, bh, ao);

    gemm_out<<<dim3(MM/128, DD/128), 256, GEMM_SMEM>>>(ao, wo, bo, out);
}

// round 14
// speedup vs baseline: 1.0103x; 1.0103x over previous
#include <cuda_runtime.h>
#include <cuda_fp16.h>
#include <cstdint>

#define BB 2
#define NN 2048
#define DD 1024
#define HH 16
#define DH 64
#define MM (BB*NN)
#define SMP 72   // smem pitch in halves (144B rows, 16B-aligned, ldsm conflict-free)

// ---------------- scratch (__device__ globals) -----------------------------
__device__ __half g_xh[(size_t)MM*DD];
__device__ __half g_wq[(size_t)DD*DD];
__device__ __half g_wk[(size_t)DD*DD];
__device__ __half g_wv[(size_t)DD*DD];
__device__ __half g_wo[(size_t)DD*DD];
__device__ __half g_bh[(size_t)BB*NN*NN];  // fp16 attn bias (unshifted)
__device__ __half g_qh[(size_t)MM*DD];     // head-major (b,h,n,dh)
__device__ __half g_kh[(size_t)MM*DD];
__device__ __half g_vh[(size_t)MM*DD];
__device__ __half g_ao[(size_t)MM*DD];     // row-major (b,n,D) fp16

// ---------------- helpers ---------------------------------------------------
__device__ __forceinline__ uint32_t s2u(const void* p) {
    uint32_t a;
    asm("{ .reg .u64 t; cvta.to.shared.u64 t, %1; cvt.u32.u64 %0, t; }" : "=r"(a) : "l"(p));
    return a;
}
__device__ __forceinline__ void ldsm4(uint32_t* r, uint32_t a) {
    asm volatile("ldmatrix.sync.aligned.m8n8.x4.shared.b16 {%0,%1,%2,%3}, [%4];"
                 : "=r"(r[0]), "=r"(r[1]), "=r"(r[2]), "=r"(r[3]) : "r"(a));
}
__device__ __forceinline__ void ldsm4t(uint32_t* r, uint32_t a) {
    asm volatile("ldmatrix.sync.aligned.m8n8.x4.trans.shared.b16 {%0,%1,%2,%3}, [%4];"
                 : "=r"(r[0]), "=r"(r[1]), "=r"(r[2]), "=r"(r[3]) : "r"(a));
}
__device__ __forceinline__ void mma16816(float* c, const uint32_t* a, const uint32_t* b) {
    asm volatile(
        "mma.sync.aligned.m16n8k16.row.col.f32.f16.f16.f32 "
        "{%0,%1,%2,%3}, {%4,%5,%6,%7}, {%8,%9}, {%0,%1,%2,%3};"
        : "+f"(c[0]), "+f"(c[1]), "+f"(c[2]), "+f"(c[3])
        : "r"(a[0]), "r"(a[1]), "r"(a[2]), "r"(a[3]), "r"(b[0]), "r"(b[1]));
}
__device__ __forceinline__ uint32_t packh2(float x, float y) {
    __half2 h = __floats2half2_rn(x, y);
    return *(uint32_t*)&h;
}
__device__ __forceinline__ void cpa16(uint32_t dst, const void* src) {
    asm volatile("cp.async.cg.shared.global [%0], [%1], 16;" :: "r"(dst), "l"(src));
}
#define CP_COMMIT() asm volatile("cp.async.commit_group;" ::: "memory")
#define CP_WAIT(n)  asm volatile("cp.async.wait_group %0;" :: "n"(n) : "memory")

// ---------------- fp32 -> fp16 converts --------------------------------------
__global__ void conv_f2h(const float* __restrict__ in, __half* __restrict__ out) {
    size_t i = (size_t)blockIdx.x * blockDim.x + threadIdx.x;
    float4 v = ((const float4*)in)[i];
    __half2* o = (__half2*)out;
    o[2*i]   = __floats2half2_rn(v.x, v.y);
    o[2*i+1] = __floats2half2_rn(v.z, v.w);
}
__global__ void conv_w4(const float* __restrict__ w0, const float* __restrict__ w1,
                        const float* __restrict__ w2, const float* __restrict__ w3,
                        __half* __restrict__ o0, __half* __restrict__ o1,
                        __half* __restrict__ o2, __half* __restrict__ o3) {
    const int z = blockIdx.y;
    const float* in = (z == 0) ? w0 : (z == 1) ? w1 : (z == 2) ? w2 : w3;
    __half* out     = (z == 0) ? o0 : (z == 1) ? o1 : (z == 2) ? o2 : o3;
    size_t i = (size_t)blockIdx.x * blockDim.x + threadIdx.x;
    float4 v = ((const float4*)in)[i];
    __half2* o = (__half2*)out;
    o[2*i]   = __floats2half2_rn(v.x, v.y);
    o[2*i+1] = __floats2half2_rn(v.z, v.w);
}

// ---------------- shared GEMM mainloop (R11 2-stage, measured fastest) ------
// 128x128 block, 256 threads, k-chunks of 64, cp.async double-buffered.
#define GEMM_MAINLOOP(A_, W_)                                                  \
    const int tid = threadIdx.x, lane = tid & 31, wid = tid >> 5;              \
    const int wm = wid >> 2, wn = wid & 3;                                     \
    const int g = lane >> 2, t4 = lane & 3;                                    \
    const int m0 = blockIdx.x * 128, e0 = blockIdx.y * 128;                    \
    const int lrow = tid >> 1, lseg = tid & 1;                                 \
    const uint32_t base = s2u(dsm);                                            \
    const uint32_t bufA0 = base, bufB0 = base + 18432;                         \
    const uint32_t bufA1 = base + 36864, bufB1 = base + 55296;                 \
    const uint32_t rowoff = (uint32_t)lrow * 144u + (uint32_t)lseg * 64u;      \
    const __half* ga = A_ + (size_t)(m0 + lrow) * DD + lseg * 32;              \
    const __half* gw = W_ + (size_t)(e0 + lrow) * DD + lseg * 32;              \
    _Pragma("unroll")                                                          \
    for (int j = 0; j < 4; j++) cpa16(bufA0 + rowoff + j*16, ga + j*8);        \
    _Pragma("unroll")                                                          \
    for (int j = 0; j < 4; j++) cpa16(bufB0 + rowoff + j*16, gw + j*8);        \
    CP_COMMIT();                                                               \
    float acc[4][4][4] = {};                                                   \
    for (int c = 0; c < 16; c++) {                                             \
        if (c + 1 < 16) {                                                      \
            uint32_t dA = (c & 1) ? bufA0 : bufA1;                             \
            uint32_t dB = (c & 1) ? bufB0 : bufB1;                             \
            const __half* sa = ga + (c + 1) * 64;                              \
            const __half* sw = gw + (c + 1) * 64;                              \
            _Pragma("unroll")                                                  \
            for (int j = 0; j < 4; j++) cpa16(dA + rowoff + j*16, sa + j*8);   \
            _Pragma("unroll")                                                  \
            for (int j = 0; j < 4; j++) cpa16(dB + rowoff + j*16, sw + j*8);   \
            CP_COMMIT();                                                       \
            CP_WAIT(1);                                                        \
        } else {                                                               \
            CP_WAIT(0);                                                        \
        }                                                                      \
        __syncthreads();                                                       \
        const uint32_t aB = (c & 1) ? bufA1 : bufA0;                           \
        const uint32_t bB = (c & 1) ? bufB1 : bufB0;                           \
        _Pragma("unroll")                                                      \
        for (int ks = 0; ks < 4; ks++) {                                       \
            uint32_t af[4][4];                                                 \
            _Pragma("unroll")                                                  \
            for (int mt = 0; mt < 4; mt++)                                     \
                ldsm4(af[mt], aB + ((wm*64 + mt*16 + (lane & 15)) * SMP        \
                                    + ks*16 + ((lane >> 4) << 3)) * 2);        \
            uint32_t bf[2][4];                                                 \
            _Pragma("unroll")                                                  \
            for (int np = 0; np < 2; np++)                                     \
                ldsm4(bf[np], bB + ((wn*32 + np*16 + ((lane >> 4) << 3)        \
                                    + (lane & 7)) * SMP                        \
                                    + ks*16 + (((lane >> 3) & 1) << 3)) * 2);  \
            _Pragma("unroll")                                                  \
            for (int mt = 0; mt < 4; mt++)                                     \
                _Pragma("unroll")                                              \
                for (int nt = 0; nt < 4; nt++)                                 \
                    mma16816(acc[mt][nt], af[mt], &bf[nt >> 1][(nt & 1) * 2]); \
        }                                                                      \
        __syncthreads();                                                       \
    }

// ---------------- fused QKV projection + LN (Q,K) ---------------------------
__global__ void __launch_bounds__(256) gemm_qkv(
    const __half* __restrict__ A,
    const __half* __restrict__ Wqp, const __half* __restrict__ Wkp, const __half* __restrict__ Wvp,
    const float* __restrict__ bqp, const float* __restrict__ bkp, const float* __restrict__ bvp,
    const float* __restrict__ qgp, const float* __restrict__ qbp,
    const float* __restrict__ kgp, const float* __restrict__ kbp,
    __half* __restrict__ qhp, __half* __restrict__ khp, __half* __restrict__ vhp)
{
    extern __shared__ char dsm[];
    const int z = blockIdx.z;
    const __half* W   = (z == 0) ? Wqp : (z == 1) ? Wkp : Wvp;
    const float* bias = (z == 0) ? bqp : (z == 1) ? bkp : bvp;

    GEMM_MAINLOOP(A, W)

    if (z == 2) {
        #pragma unroll
        for (int mt = 0; mt < 4; mt++) {
            #pragma unroll
            for (int nt = 0; nt < 4; nt++) {
                int m = m0 + wm*64 + mt*16 + g;
                int e = e0 + wn*32 + nt*8 + 2*t4;
                float b0 = bias[e], b1 = bias[e + 1];
                int hh = e >> 6, hd = e & 63;
                int b_ = m >> 11, n = m & 2047;
                *(__half2*)(vhp + (((size_t)b_*HH + hh)*NN + n)     * DH + hd) =
                    __floats2half2_rn(acc[mt][nt][0] + b0, acc[mt][nt][1] + b1);
                *(__half2*)(vhp + (((size_t)b_*HH + hh)*NN + n + 8) * DH + hd) =
                    __floats2half2_rn(acc[mt][nt][2] + b0, acc[mt][nt][3] + b1);
            }
        }
    } else {
        float* stage = (float*)dsm;
        #pragma unroll
        for (int mt = 0; mt < 4; mt++) {
            #pragma unroll
            for (int nt = 0; nt < 4; nt++) {
                int r = wm*64 + mt*16 + g;
                int e = wn*32 + nt*8 + 2*t4;
                float b0 = bias[e0 + e], b1 = bias[e0 + e + 1];
                *(float2*)&stage[r*132 + e] =
                    make_float2(acc[mt][nt][0] + b0, acc[mt][nt][1] + b1);
                *(float2*)&stage[(r + 8)*132 + e] =
                    make_float2(acc[mt][nt][2] + b0, acc[mt][nt][3] + b1);
            }
        }
        __syncthreads();
        const float* gam = z ? kgp : qgp;
        const float* bet = z ? kbp : qbp;
        __half* outp = z ? khp : qhp;
        float gm0 = gam[lane], gm1 = gam[lane + 32];
        float bt0 = bet[lane], bt1 = bet[lane + 32];
        #pragma unroll 4
        for (int t = 0; t < 32; t++) {
            int task = t*8 + wid;
            int r = task >> 1, hh = task & 1;
            float v0 = stage[r*132 + hh*64 + lane];
            float v1 = stage[r*132 + hh*64 + lane + 32];
            float s = v0 + v1;
            #pragma unroll
            for (int o = 16; o > 0; o >>= 1) s += __shfl_xor_sync(0xffffffffu, s, o);
            float mu = s * (1.0f / 64.0f);
            float d0 = v0 - mu, d1 = v1 - mu;
            float vs = d0*d0 + d1*d1;
            #pragma unroll
            for (int o = 16; o > 0; o >>= 1) vs += __shfl_xor_sync(0xffffffffu, vs, o);
            float rs = rsqrtf(vs * (1.0f / 64.0f) + 1e-6f);
            int m = m0 + r, b_ = m >> 11, n = m & 2047;
            int hglob = (e0 >> 6) + hh;
            __half* dst = outp + (((size_t)b_*HH + hglob)*NN + n) * DH;
            dst[lane]      = __float2half_rn(d0 * rs * gm0 + bt0);
            dst[lane + 32] = __float2half_rn(d1 * rs * gm1 + bt1);
        }
    }
}

// ---------------- output projection (fp32 row-major out) --------------------
__global__ void __launch_bounds__(256) gemm_out(
    const __half* __restrict__ A, const __half* __restrict__ W,
    const float* __restrict__ bias, float* __restrict__ outf)
{
    extern __shared__ char dsm[];
    GEMM_MAINLOOP(A, W)
    #pragma unroll
    for (int mt = 0; mt < 4; mt++) {
        #pragma unroll
        for (int nt = 0; nt < 4; nt++) {
            int m = m0 + wm*64 + mt*16 + g;
            int e = e0 + wn*32 + nt*8 + 2*t4;
            float b0 = bias[e], b1 = bias[e + 1];
            *(float2*)(outf + (size_t)m * DD + e) =
                make_float2(acc[mt][nt][0] + b0, acc[mt][nt][1] + b1);
            *(float2*)(outf + (size_t)(m + 8) * DD + e) =
                make_float2(acc[mt][nt][2] + b0, acc[mt][nt][3] + b1);
        }
    }
}

// ---------------- attention: fused QK->exp->PV, 4 blocks/SM target ----------
// 128 thr, 64q tile, 64k chunks, bias in smem (unshifted fp16).
// smem bytes (55296 total): K0@0 | V0@9216 | B0@18432 | K1@27648 | V1@36864 |
// Q@46080 (reused as B1 after qf fragment load).
__global__ void __launch_bounds__(128, 4) attn_hmma(const __half* __restrict__ q,
                                                    const __half* __restrict__ k,
                                                    const __half* __restrict__ v,
                                                    const __half* __restrict__ bias16,
                                                    __half* __restrict__ out)
{
    extern __shared__ __half sm[];
    const int tid = threadIdx.x, lane = tid & 31, wid = tid >> 5;
    const int g = lane >> 2, t4 = lane & 3;
    const int qt = blockIdx.x, h = blockIdx.y, b = blockIdx.z;
    const int lrow = tid >> 1, lseg = tid & 1;   // 64 rows x 2 segments

    const __half* qp = q + (((size_t)b*HH + h)*NN + qt*64) * DH;
    const __half* kp = k + ((size_t)b*HH + h)*NN * DH;
    const __half* vp = v + ((size_t)b*HH + h)*NN * DH;
    const __half* gb = bias16 + ((size_t)b*NN + qt*64 + lrow) * NN + lseg * 32;

    const uint32_t base = s2u(sm);
    const uint32_t kS0 = base,         vS0 = base + 9216,  bS0 = base + 18432;
    const uint32_t kS1 = base + 27648, vS1 = base + 36864;
    const uint32_t qS  = base + 46080;          // doubles as B1 after qf load
    const uint32_t bS1 = base + 46080;
    const uint32_t rowoff = (uint32_t)lrow * 144u + (uint32_t)lseg * 64u;

    // stage Q + prefetch chunk 0 (K, V, bias)
    {
        const __half* qs = qp + (size_t)lrow * DH + lseg * 32;
        const __half* ks = kp + (size_t)lrow * DH + lseg * 32;
        const __half* vs = vp + (size_t)lrow * DH + lseg * 32;
        #pragma unroll
        for (int j = 0; j < 4; j++) cpa16(qS  + rowoff + j*16, qs + j*8);
        #pragma unroll
        for (int j = 0; j < 4; j++) cpa16(kS0 + rowoff + j*16, ks + j*8);
        #pragma unroll
        for (int j = 0; j < 4; j++) cpa16(vS0 + rowoff + j*16, vs + j*8);
        #pragma unroll
        for (int j = 0; j < 4; j++) cpa16(bS0 + rowoff + j*16, gb + j*8);
        CP_COMMIT();
    }
    CP_WAIT(0);
    __syncthreads();

    uint32_t qf[4][4];
    #pragma unroll
    for (int ks = 0; ks < 4; ks++)
        ldsm4(qf[ks], qS + ((wid*16 + (lane & 15)) * SMP
                            + ks*16 + ((lane >> 4) << 3)) * 2);
    __syncthreads();   // qS fully consumed by all warps; safe to reuse as B1

    float o[8][4] = {};
    float l0 = 0.0f, l1 = 0.0f;
    const int r0 = wid * 16 + g;                 // local query row (first 8-group)

    for (int c = 0; c < 32; c++) {               // 32 chunks of 64 keys
        if (c + 1 < 32) {
            const uint32_t dk = ((c + 1) & 1) ? kS1 : kS0;
            const uint32_t dv = ((c + 1) & 1) ? vS1 : vS0;
            const uint32_t db = ((c + 1) & 1) ? bS1 : bS0;
            const __half* ks = kp + ((size_t)(c + 1)*64 + lrow) * DH + lseg * 32;
            const __half* vs = vp + ((size_t)(c + 1)*64 + lrow) * DH + lseg * 32;
            const __half* bs = gb + (c + 1) * 64;
            #pragma unroll
            for (int j = 0; j < 4; j++) cpa16(dk + rowoff + j*16, ks + j*8);
            #pragma unroll
            for (int j = 0; j < 4; j++) cpa16(dv + rowoff + j*16, vs + j*8);
            #pragma unroll
            for (int j = 0; j < 4; j++) cpa16(db + rowoff + j*16, bs + j*8);
            CP_COMMIT();
            CP_WAIT(1);
        } else {
            CP_WAIT(0);
        }
        __syncthreads();
        const uint32_t kB = (c & 1) ? kS1 : kS0;
        const uint32_t vB = (c & 1) ? vS1 : vS0;
        const __half* bsm = sm + ((c & 1) ? 23040 : 9216);   // half-index of bias buf

        #pragma unroll
        for (int np = 0; np < 4; np++) {         // 4 groups of 16 keys, fused
            float s[2][4] = {};
            #pragma unroll
            for (int ks = 0; ks < 4; ks++) {
                uint32_t bfr[4];
                ldsm4(bfr, kB + ((np*16 + ((lane >> 4) << 3) + (lane & 7)) * SMP
                                 + ks*16 + (((lane >> 3) & 1) << 3)) * 2);
                mma16816(s[0], qf[ks], bfr);
                mma16816(s[1], qf[ks], bfr + 2);
            }
            uint32_t a[4];
            #pragma unroll
            for (int e = 0; e < 2; e++) {
                int col = (2*np + e)*8 + 2*t4;   // local key col
                float2 bb0 = __half22float2(*(const __half2*)(bsm + r0*SMP + col));
                float2 bb1 = __half22float2(*(const __half2*)(bsm + (r0 + 8)*SMP + col));
                float p0 = __expf(fmaf(s[e][0], 0.125f, bb0.x) - 6.0f);
                float p1 = __expf(fmaf(s[e][1], 0.125f, bb0.y) - 6.0f);
                float p2 = __expf(fmaf(s[e][2], 0.125f, bb1.x) - 6.0f);
                float p3 = __expf(fmaf(s[e][3], 0.125f, bb1.y) - 6.0f);
                l0 += p0 + p1;
                l1 += p2 + p3;
                a[2*e]     = packh2(p0, p1);
                a[2*e + 1] = packh2(p2, p3);
            }
            #pragma unroll
            for (int dp = 0; dp < 4; dp++) {
                uint32_t bfr[4];
                ldsm4t(bfr, vB + ((np*16 + (lane & 15)) * SMP
                                  + dp*16 + ((lane >> 4) << 3)) * 2);
                mma16816(o[2*dp],     a, bfr);
                mma16816(o[2*dp + 1], a, bfr + 2);
            }
        }
        __syncthreads();
    }

    l0 += __shfl_xor_sync(0xffffffffu, l0, 1);
    l0 += __shfl_xor_sync(0xffffffffu, l0, 2);
    l1 += __shfl_xor_sync(0xffffffffu, l1, 1);
    l1 += __shfl_xor_sync(0xffffffffu, l1, 2);
    float inv0 = 1.0f / l0, inv1 = 1.0f / l1;

    __half* or0 = out + ((size_t)b*NN + qt*64 + wid*16 + g) * DD + h * DH;
    __half* or1 = or0 + 8 * DD;
    #pragma unroll
    for (int dt = 0; dt < 8; dt++) {
        int d = dt*8 + 2*t4;
        *(__half2*)(or0 + d) = __floats2half2_rn(o[dt][0] * inv0, o[dt][1] * inv0);
        *(__half2*)(or1 + d) = __floats2half2_rn(o[dt][2] * inv1, o[dt][3] * inv1);
    }
}

// ---------------------------------------------------------------------------
extern "C" void kernel_launch(void* const* d_in, const int* in_sizes, int n_in,
                              void* d_out, int out_size)
{
    const float* x  = (const float*)d_in[0];
    const float* ab = (const float*)d_in[1];
    const float* Wq = (const float*)d_in[2];
    const float* bq = (const float*)d_in[3];
    const float* Wk = (const float*)d_in[4];
    const float* bk = (const float*)d_in[5];
    const float* Wv = (const float*)d_in[6];
    const float* bv = (const float*)d_in[7];
    const float* Wo = (const float*)d_in[8];
    const float* bo = (const float*)d_in[9];
    const float* qg = (const float*)d_in[10];
    const float* qb = (const float*)d_in[11];
    const float* kg = (const float*)d_in[12];
    const float* kb = (const float*)d_in[13];
    float* out = (float*)d_out;

    __half *xh, *wq, *wk, *wv, *wo, *bh, *qh, *kh, *vh, *ao;
    cudaGetSymbolAddress((void**)&xh, g_xh);
    cudaGetSymbolAddress((void**)&wq, g_wq);
    cudaGetSymbolAddress((void**)&wk, g_wk);
    cudaGetSymbolAddress((void**)&wv, g_wv);
    cudaGetSymbolAddress((void**)&wo, g_wo);
    cudaGetSymbolAddress((void**)&bh, g_bh);
    cudaGetSymbolAddress((void**)&qh, g_qh);
    cudaGetSymbolAddress((void**)&kh, g_kh);
    cudaGetSymbolAddress((void**)&vh, g_vh);
    cudaGetSymbolAddress((void**)&ao, g_ao);

    const int GEMM_SMEM = 73728;
    const int ATTN_SMEM = 55296;
    cudaFuncSetAttribute(gemm_qkv,  cudaFuncAttributeMaxDynamicSharedMemorySize, GEMM_SMEM);
    cudaFuncSetAttribute(gemm_out,  cudaFuncAttributeMaxDynamicSharedMemorySize, GEMM_SMEM);
    cudaFuncSetAttribute(attn_hmma, cudaFuncAttributeMaxDynamicSharedMemorySize, ATTN_SMEM);

    conv_f2h<<<(MM*DD)/1024, 256>>>(x, xh);
    conv_f2h<<<(BB*NN*NN)/1024, 256>>>(ab, bh);
    conv_w4<<<dim3((DD*DD)/1024, 4), 256>>>(Wq, Wk, Wv, Wo, wq, wk, wv, wo);

    gemm_qkv<<<dim3(MM/128, DD/128, 3), 256, GEMM_SMEM>>>(
        xh, wq, wk, wv, bq, bk, bv, qg, qb, kg, kb, qh, kh, vh);

    attn_hmma<<<dim3(NN/64, HH, BB), 128, ATTN_SMEM>>>(qh, kh, vh, bh, ao);

    gemm_out<<<dim3(MM/128, DD/128), 256, GEMM_SMEM>>>(ao, wo, bo, out);
}

// round 15
// speedup vs baseline: 1.0114x; 1.0011x over previous
#include <cuda_runtime.h>
#include <cuda_fp16.h>
#include <cstdint>

#define BB 2
#define NN 2048
#define DD 1024
#define HH 16
#define DH 64
#define MM (BB*NN)
#define SMP 72   // smem pitch in halves (144B rows, 16B-aligned, ldsm conflict-free)

// ---------------- scratch (__device__ globals) -----------------------------
__device__ __half g_xh[(size_t)MM*DD];
__device__ __half g_wq[(size_t)DD*DD];
__device__ __half g_wk[(size_t)DD*DD];
__device__ __half g_wv[(size_t)DD*DD];
__device__ __half g_wo[(size_t)DD*DD];
__device__ __half g_bh[(size_t)BB*NN*NN];  // fp16 attn bias (unshifted)
__device__ __half g_qh[(size_t)MM*DD];     // head-major (b,h,n,dh)
__device__ __half g_kh[(size_t)MM*DD];
__device__ __half g_vh[(size_t)MM*DD];
__device__ __half g_ao[(size_t)MM*DD];     // row-major (b,n,D) fp16

// ---------------- helpers ---------------------------------------------------
__device__ __forceinline__ uint32_t s2u(const void* p) {
    uint32_t a;
    asm("{ .reg .u64 t; cvta.to.shared.u64 t, %1; cvt.u32.u64 %0, t; }" : "=r"(a) : "l"(p));
    return a;
}
__device__ __forceinline__ void ldsm4(uint32_t* r, uint32_t a) {
    asm volatile("ldmatrix.sync.aligned.m8n8.x4.shared.b16 {%0,%1,%2,%3}, [%4];"
                 : "=r"(r[0]), "=r"(r[1]), "=r"(r[2]), "=r"(r[3]) : "r"(a));
}
__device__ __forceinline__ void ldsm4t(uint32_t* r, uint32_t a) {
    asm volatile("ldmatrix.sync.aligned.m8n8.x4.trans.shared.b16 {%0,%1,%2,%3}, [%4];"
                 : "=r"(r[0]), "=r"(r[1]), "=r"(r[2]), "=r"(r[3]) : "r"(a));
}
__device__ __forceinline__ void mma16816(float* c, const uint32_t* a, const uint32_t* b) {
    asm volatile(
        "mma.sync.aligned.m16n8k16.row.col.f32.f16.f16.f32 "
        "{%0,%1,%2,%3}, {%4,%5,%6,%7}, {%8,%9}, {%0,%1,%2,%3};"
        : "+f"(c[0]), "+f"(c[1]), "+f"(c[2]), "+f"(c[3])
        : "r"(a[0]), "r"(a[1]), "r"(a[2]), "r"(a[3]), "r"(b[0]), "r"(b[1]));
}
__device__ __forceinline__ uint32_t packh2(float x, float y) {
    __half2 h = __floats2half2_rn(x, y);
    return *(uint32_t*)&h;
}
__device__ __forceinline__ void cpa16(uint32_t dst, const void* src) {
    asm volatile("cp.async.cg.shared.global [%0], [%1], 16;" :: "r"(dst), "l"(src));
}
#define CP_COMMIT() asm volatile("cp.async.commit_group;" ::: "memory")
#define CP_WAIT(n)  asm volatile("cp.async.wait_group %0;" :: "n"(n) : "memory")

// ---------------- fp32 -> fp16 converts --------------------------------------
__global__ void conv_f2h(const float* __restrict__ in, __half* __restrict__ out) {
    size_t i = (size_t)blockIdx.x * blockDim.x + threadIdx.x;
    float4 v = ((const float4*)in)[i];
    __half2* o = (__half2*)out;
    o[2*i]   = __floats2half2_rn(v.x, v.y);
    o[2*i+1] = __floats2half2_rn(v.z, v.w);
}
__global__ void conv_w4(const float* __restrict__ w0, const float* __restrict__ w1,
                        const float* __restrict__ w2, const float* __restrict__ w3,
                        __half* __restrict__ o0, __half* __restrict__ o1,
                        __half* __restrict__ o2, __half* __restrict__ o3) {
    const int z = blockIdx.y;
    const float* in = (z == 0) ? w0 : (z == 1) ? w1 : (z == 2) ? w2 : w3;
    __half* out     = (z == 0) ? o0 : (z == 1) ? o1 : (z == 2) ? o2 : o3;
    size_t i = (size_t)blockIdx.x * blockDim.x + threadIdx.x;
    float4 v = ((const float4*)in)[i];
    __half2* o = (__half2*)out;
    o[2*i]   = __floats2half2_rn(v.x, v.y);
    o[2*i+1] = __floats2half2_rn(v.z, v.w);
}

// ---------------- shared GEMM mainloop (R11 2-stage, measured fastest) ------
// 128x128 block, 256 threads, k-chunks of 64, cp.async double-buffered.
#define GEMM_MAINLOOP(A_, W_)                                                  \
    const int tid = threadIdx.x, lane = tid & 31, wid = tid >> 5;              \
    const int wm = wid >> 2, wn = wid & 3;                                     \
    const int g = lane >> 2, t4 = lane & 3;                                    \
    const int m0 = blockIdx.x * 128, e0 = blockIdx.y * 128;                    \
    const int lrow = tid >> 1, lseg = tid & 1;                                 \
    const uint32_t base = s2u(dsm);                                            \
    const uint32_t bufA0 = base, bufB0 = base + 18432;                         \
    const uint32_t bufA1 = base + 36864, bufB1 = base + 55296;                 \
    const uint32_t rowoff = (uint32_t)lrow * 144u + (uint32_t)lseg * 64u;      \
    const __half* ga = A_ + (size_t)(m0 + lrow) * DD + lseg * 32;              \
    const __half* gw = W_ + (size_t)(e0 + lrow) * DD + lseg * 32;              \
    _Pragma("unroll")                                                          \
    for (int j = 0; j < 4; j++) cpa16(bufA0 + rowoff + j*16, ga + j*8);        \
    _Pragma("unroll")                                                          \
    for (int j = 0; j < 4; j++) cpa16(bufB0 + rowoff + j*16, gw + j*8);        \
    CP_COMMIT();                                                               \
    float acc[4][4][4] = {};                                                   \
    for (int c = 0; c < 16; c++) {                                             \
        if (c + 1 < 16) {                                                      \
            uint32_t dA = (c & 1) ? bufA0 : bufA1;                             \
            uint32_t dB = (c & 1) ? bufB0 : bufB1;                             \
            const __half* sa = ga + (c + 1) * 64;                              \
            const __half* sw = gw + (c + 1) * 64;                              \
            _Pragma("unroll")                                                  \
            for (int j = 0; j < 4; j++) cpa16(dA + rowoff + j*16, sa + j*8);   \
            _Pragma("unroll")                                                  \
            for (int j = 0; j < 4; j++) cpa16(dB + rowoff + j*16, sw + j*8);   \
            CP_COMMIT();                                                       \
            CP_WAIT(1);                                                        \
        } else {                                                               \
            CP_WAIT(0);                                                        \
        }                                                                      \
        __syncthreads();                                                       \
        const uint32_t aB = (c & 1) ? bufA1 : bufA0;                           \
        const uint32_t bB = (c & 1) ? bufB1 : bufB0;                           \
        _Pragma("unroll")                                                      \
        for (int ks = 0; ks < 4; ks++) {                                       \
            uint32_t af[4][4];                                                 \
            _Pragma("unroll")                                                  \
            for (int mt = 0; mt < 4; mt++)                                     \
                ldsm4(af[mt], aB + ((wm*64 + mt*16 + (lane & 15)) * SMP        \
                                    + ks*16 + ((lane >> 4) << 3)) * 2);        \
            uint32_t bf[2][4];                                                 \
            _Pragma("unroll")                                                  \
            for (int np = 0; np < 2; np++)                                     \
                ldsm4(bf[np], bB + ((wn*32 + np*16 + ((lane >> 4) << 3)        \
                                    + (lane & 7)) * SMP                        \
                                    + ks*16 + (((lane >> 3) & 1) << 3)) * 2);  \
            _Pragma("unroll")                                                  \
            for (int mt = 0; mt < 4; mt++)                                     \
                _Pragma("unroll")                                              \
                for (int nt = 0; nt < 4; nt++)                                 \
                    mma16816(acc[mt][nt], af[mt], &bf[nt >> 1][(nt & 1) * 2]); \
        }                                                                      \
        __syncthreads();                                                       \
    }

// ---------------- fused QKV projection + LN (Q,K) ---------------------------
__global__ void __launch_bounds__(256) gemm_qkv(
    const __half* __restrict__ A,
    const __half* __restrict__ Wqp, const __half* __restrict__ Wkp, const __half* __restrict__ Wvp,
    const float* __restrict__ bqp, const float* __restrict__ bkp, const float* __restrict__ bvp,
    const float* __restrict__ qgp, const float* __restrict__ qbp,
    const float* __restrict__ kgp, const float* __restrict__ kbp,
    __half* __restrict__ qhp, __half* __restrict__ khp, __half* __restrict__ vhp)
{
    extern __shared__ char dsm[];
    const int z = blockIdx.z;
    const __half* W   = (z == 0) ? Wqp : (z == 1) ? Wkp : Wvp;
    const float* bias = (z == 0) ? bqp : (z == 1) ? bkp : bvp;

    GEMM_MAINLOOP(A, W)

    if (z == 2) {
        #pragma unroll
        for (int mt = 0; mt < 4; mt++) {
            #pragma unroll
            for (int nt = 0; nt < 4; nt++) {
                int m = m0 + wm*64 + mt*16 + g;
                int e = e0 + wn*32 + nt*8 + 2*t4;
                float b0 = bias[e], b1 = bias[e + 1];
                int hh = e >> 6, hd = e & 63;
                int b_ = m >> 11, n = m & 2047;
                *(__half2*)(vhp + (((size_t)b_*HH + hh)*NN + n)     * DH + hd) =
                    __floats2half2_rn(acc[mt][nt][0] + b0, acc[mt][nt][1] + b1);
                *(__half2*)(vhp + (((size_t)b_*HH + hh)*NN + n + 8) * DH + hd) =
                    __floats2half2_rn(acc[mt][nt][2] + b0, acc[mt][nt][3] + b1);
            }
        }
    } else {
        float* stage = (float*)dsm;
        #pragma unroll
        for (int mt = 0; mt < 4; mt++) {
            #pragma unroll
            for (int nt = 0; nt < 4; nt++) {
                int r = wm*64 + mt*16 + g;
                int e = wn*32 + nt*8 + 2*t4;
                float b0 = bias[e0 + e], b1 = bias[e0 + e + 1];
                *(float2*)&stage[r*132 + e] =
                    make_float2(acc[mt][nt][0] + b0, acc[mt][nt][1] + b1);
                *(float2*)&stage[(r + 8)*132 + e] =
                    make_float2(acc[mt][nt][2] + b0, acc[mt][nt][3] + b1);
            }
        }
        __syncthreads();
        const float* gam = z ? kgp : qgp;
        const float* bet = z ? kbp : qbp;
        __half* outp = z ? khp : qhp;
        float gm0 = gam[lane], gm1 = gam[lane + 32];
        float bt0 = bet[lane], bt1 = bet[lane + 32];
        #pragma unroll 4
        for (int t = 0; t < 32; t++) {
            int task = t*8 + wid;
            int r = task >> 1, hh = task & 1;
            float v0 = stage[r*132 + hh*64 + lane];
            float v1 = stage[r*132 + hh*64 + lane + 32];
            float s = v0 + v1;
            #pragma unroll
            for (int o = 16; o > 0; o >>= 1) s += __shfl_xor_sync(0xffffffffu, s, o);
            float mu = s * (1.0f / 64.0f);
            float d0 = v0 - mu, d1 = v1 - mu;
            float vs = d0*d0 + d1*d1;
            #pragma unroll
            for (int o = 16; o > 0; o >>= 1) vs += __shfl_xor_sync(0xffffffffu, vs, o);
            float rs = rsqrtf(vs * (1.0f / 64.0f) + 1e-6f);
            int m = m0 + r, b_ = m >> 11, n = m & 2047;
            int hglob = (e0 >> 6) + hh;
            __half* dst = outp + (((size_t)b_*HH + hglob)*NN + n) * DH;
            dst[lane]      = __float2half_rn(d0 * rs * gm0 + bt0);
            dst[lane + 32] = __float2half_rn(d1 * rs * gm1 + bt1);
        }
    }
}

// ---------------- output projection (fp32 row-major out) --------------------
__global__ void __launch_bounds__(256) gemm_out(
    const __half* __restrict__ A, const __half* __restrict__ W,
    const float* __restrict__ bias, float* __restrict__ outf)
{
    extern __shared__ char dsm[];
    GEMM_MAINLOOP(A, W)
    #pragma unroll
    for (int mt = 0; mt < 4; mt++) {
        #pragma unroll
        for (int nt = 0; nt < 4; nt++) {
            int m = m0 + wm*64 + mt*16 + g;
            int e = e0 + wn*32 + nt*8 + 2*t4;
            float b0 = bias[e], b1 = bias[e + 1];
            *(float2*)(outf + (size_t)m * DD + e) =
                make_float2(acc[mt][nt][0] + b0, acc[mt][nt][1] + b1);
            *(float2*)(outf + (size_t)(m + 8) * DD + e) =
                make_float2(acc[mt][nt][2] + b0, acc[mt][nt][3] + b1);
        }
    }
}

// ---------------- attention: pipelined QK(np+1) || exp(np)+PV(np) -----------
// 128 thr, 64q tile, 64k chunks, single barrier per chunk, bias fp16 in smem.
// smem bytes (55296): K0@0 | V0@9216 | B0@18432 | K1@27648 | V1@36864 |
// Q@46080 (reused as B1 after qf fragment load).
__global__ void __launch_bounds__(128, 3) attn_hmma(const __half* __restrict__ q,
                                                    const __half* __restrict__ k,
                                                    const __half* __restrict__ v,
                                                    const __half* __restrict__ bias16,
                                                    __half* __restrict__ out)
{
    extern __shared__ __half sm[];
    const int tid = threadIdx.x, lane = tid & 31, wid = tid >> 5;
    const int g = lane >> 2, t4 = lane & 3;
    const int qt = blockIdx.x, h = blockIdx.y, b = blockIdx.z;
    const int lrow = tid >> 1, lseg = tid & 1;   // 64 rows x 2 segments

    const __half* qp = q + (((size_t)b*HH + h)*NN + qt*64) * DH;
    const __half* kp = k + ((size_t)b*HH + h)*NN * DH;
    const __half* vp = v + ((size_t)b*HH + h)*NN * DH;
    const __half* gb = bias16 + ((size_t)b*NN + qt*64 + lrow) * NN + lseg * 32;

    const uint32_t base = s2u(sm);
    const uint32_t kS0 = base,         vS0 = base + 9216,  bS0 = base + 18432;
    const uint32_t kS1 = base + 27648, vS1 = base + 36864;
    const uint32_t qS  = base + 46080;          // doubles as B1 after qf load
    const uint32_t bS1 = base + 46080;
    const uint32_t rowoff = (uint32_t)lrow * 144u + (uint32_t)lseg * 64u;

    // stage Q + prefetch chunk 0 (K, V, bias)
    {
        const __half* qs = qp + (size_t)lrow * DH + lseg * 32;
        const __half* ks = kp + (size_t)lrow * DH + lseg * 32;
        const __half* vs = vp + (size_t)lrow * DH + lseg * 32;
        #pragma unroll
        for (int j = 0; j < 4; j++) cpa16(qS  + rowoff + j*16, qs + j*8);
        #pragma unroll
        for (int j = 0; j < 4; j++) cpa16(kS0 + rowoff + j*16, ks + j*8);
        #pragma unroll
        for (int j = 0; j < 4; j++) cpa16(vS0 + rowoff + j*16, vs + j*8);
        #pragma unroll
        for (int j = 0; j < 4; j++) cpa16(bS0 + rowoff + j*16, gb + j*8);
        CP_COMMIT();
    }
    CP_WAIT(0);
    __syncthreads();

    uint32_t qf[4][4];
    #pragma unroll
    for (int ks = 0; ks < 4; ks++)
        ldsm4(qf[ks], qS + ((wid*16 + (lane & 15)) * SMP
                            + ks*16 + ((lane >> 4) << 3)) * 2);
    __syncthreads();   // qS fully consumed by all warps; safe to reuse as B1

    float o[8][4] = {};
    float l0 = 0.0f, l1 = 0.0f;
    const int r0 = wid * 16 + g;                 // local query row (first 8-group)

    for (int c = 0; c < 32; c++) {               // 32 chunks of 64 keys
        CP_WAIT(0);          // loads for chunk c (issued at iter c-1) landed
        __syncthreads();     // data visible to all; all warps done with chunk c-1
        if (c + 1 < 32) {    // prefetch c+1 into the buffer freed by chunk c-1
            const uint32_t dk = ((c + 1) & 1) ? kS1 : kS0;
            const uint32_t dv = ((c + 1) & 1) ? vS1 : vS0;
            const uint32_t db = ((c + 1) & 1) ? bS1 : bS0;
            const __half* ks = kp + ((size_t)(c + 1)*64 + lrow) * DH + lseg * 32;
            const __half* vs = vp + ((size_t)(c + 1)*64 + lrow) * DH + lseg * 32;
            const __half* bs = gb + (c + 1) * 64;
            #pragma unroll
            for (int j = 0; j < 4; j++) cpa16(dk + rowoff + j*16, ks + j*8);
            #pragma unroll
            for (int j = 0; j < 4; j++) cpa16(dv + rowoff + j*16, vs + j*8);
            #pragma unroll
            for (int j = 0; j < 4; j++) cpa16(db + rowoff + j*16, bs + j*8);
            CP_COMMIT();
        }
        const uint32_t kB = (c & 1) ? kS1 : kS0;
        const uint32_t vB = (c & 1) ? vS1 : vS0;
        const __half* bsm = sm + ((c & 1) ? 23040 : 9216);   // half-index of bias buf

        // software pipeline: S(np+1) overlaps exp(np)+PV(np)
        float s_cur[2][4] = {};
        #pragma unroll
        for (int ks = 0; ks < 4; ks++) {
            uint32_t bfr[4];
            ldsm4(bfr, kB + ((((lane >> 4) << 3) + (lane & 7)) * SMP
                             + ks*16 + (((lane >> 3) & 1) << 3)) * 2);
            mma16816(s_cur[0], qf[ks], bfr);
            mma16816(s_cur[1], qf[ks], bfr + 2);
        }
        #pragma unroll
        for (int np = 0; np < 4; np++) {
            float s_nxt[2][4] = {};
            if (np < 3) {
                #pragma unroll
                for (int ks = 0; ks < 4; ks++) {
                    uint32_t bfr[4];
                    ldsm4(bfr, kB + (((np+1)*16 + ((lane >> 4) << 3) + (lane & 7)) * SMP
                                     + ks*16 + (((lane >> 3) & 1) << 3)) * 2);
                    mma16816(s_nxt[0], qf[ks], bfr);
                    mma16816(s_nxt[1], qf[ks], bfr + 2);
                }
            }
            uint32_t a[4];
            #pragma unroll
            for (int e = 0; e < 2; e++) {
                int col = (2*np + e)*8 + 2*t4;   // local key col
                float2 bb0 = __half22float2(*(const __half2*)(bsm + r0*SMP + col));
                float2 bb1 = __half22float2(*(const __half2*)(bsm + (r0 + 8)*SMP + col));
                float p0 = __expf(fmaf(s_cur[e][0], 0.125f, bb0.x) - 6.0f);
                float p1 = __expf(fmaf(s_cur[e][1], 0.125f, bb0.y) - 6.0f);
                float p2 = __expf(fmaf(s_cur[e][2], 0.125f, bb1.x) - 6.0f);
                float p3 = __expf(fmaf(s_cur[e][3], 0.125f, bb1.y) - 6.0f);
                l0 += p0 + p1;
                l1 += p2 + p3;
                a[2*e]     = packh2(p0, p1);
                a[2*e + 1] = packh2(p2, p3);
            }
            #pragma unroll
            for (int dp = 0; dp < 4; dp++) {
                uint32_t bfr[4];
                ldsm4t(bfr, vB + ((np*16 + (lane & 15)) * SMP
                                  + dp*16 + ((lane >> 4) << 3)) * 2);
                mma16816(o[2*dp],     a, bfr);
                mma16816(o[2*dp + 1], a, bfr + 2);
            }
            #pragma unroll
            for (int e = 0; e < 2; e++)
                #pragma unroll
                for (int t = 0; t < 4; t++) s_cur[e][t] = s_nxt[e][t];
        }
    }

    l0 += __shfl_xor_sync(0xffffffffu, l0, 1);
    l0 += __shfl_xor_sync(0xffffffffu, l0, 2);
    l1 += __shfl_xor_sync(0xffffffffu, l1, 1);
    l1 += __shfl_xor_sync(0xffffffffu, l1, 2);
    float inv0 = 1.0f / l0, inv1 = 1.0f / l1;

    __half* or0 = out + ((size_t)b*NN + qt*64 + wid*16 + g) * DD + h * DH;
    __half* or1 = or0 + 8 * DD;
    #pragma unroll
    for (int dt = 0; dt < 8; dt++) {
        int d = dt*8 + 2*t4;
        *(__half2*)(or0 + d) = __floats2half2_rn(o[dt][0] * inv0, o[dt][1] * inv0);
        *(__half2*)(or1 + d) = __floats2half2_rn(o[dt][2] * inv1, o[dt][3] * inv1);
    }
}

// ---------------------------------------------------------------------------
extern "C" void kernel_launch(void* const* d_in, const int* in_sizes, int n_in,
                              void* d_out, int out_size)
{
    const float* x  = (const float*)d_in[0];
    const float* ab = (const float*)d_in[1];
    const float* Wq = (const float*)d_in[2];
    const float* bq = (const float*)d_in[3];
    const float* Wk = (const float*)d_in[4];
    const float* bk = (const float*)d_in[5];
    const float* Wv = (const float*)d_in[6];
    const float* bv = (const float*)d_in[7];
    const float* Wo = (const float*)d_in[8];
    const float* bo = (const float*)d_in[9];
    const float* qg = (const float*)d_in[10];
    const float* qb = (const float*)d_in[11];
    const float* kg = (const float*)d_in[12];
    const float* kb = (const float*)d_in[13];
    float* out = (float*)d_out;

    __half *xh, *wq, *wk, *wv, *wo, *bh, *qh, *kh, *vh, *ao;
    cudaGetSymbolAddress((void**)&xh, g_xh);
    cudaGetSymbolAddress((void**)&wq, g_wq);
    cudaGetSymbolAddress((void**)&wk, g_wk);
    cudaGetSymbolAddress((void**)&wv, g_wv);
    cudaGetSymbolAddress((void**)&wo, g_wo);
    cudaGetSymbolAddress((void**)&bh, g_bh);
    cudaGetSymbolAddress((void**)&qh, g_qh);
    cudaGetSymbolAddress((void**)&kh, g_kh);
    cudaGetSymbolAddress((void**)&vh, g_vh);
    cudaGetSymbolAddress((void**)&ao, g_ao);

    const int GEMM_SMEM = 73728;
    const int ATTN_SMEM = 55296;
    cudaFuncSetAttribute(gemm_qkv,  cudaFuncAttributeMaxDynamicSharedMemorySize, GEMM_SMEM);
    cudaFuncSetAttribute(gemm_out,  cudaFuncAttributeMaxDynamicSharedMemorySize, GEMM_SMEM);
    cudaFuncSetAttribute(attn_hmma, cudaFuncAttributeMaxDynamicSharedMemorySize, ATTN_SMEM);

    conv_f2h<<<(MM*DD)/1024, 256>>>(x, xh);
    conv_f2h<<<(BB*NN*NN)/1024, 256>>>(ab, bh);
    conv_w4<<<dim3((DD*DD)/1024, 4), 256>>>(Wq, Wk, Wv, Wo, wq, wk, wv, wo);

    gemm_qkv<<<dim3(MM/128, DD/128, 3), 256, GEMM_SMEM>>>(
        xh, wq, wk, wv, bq, bk, bv, qg, qb, kg, kb, qh, kh, vh);

    attn_hmma<<<dim3(NN/64, HH, BB), 128, ATTN_SMEM>>>(qh, kh, vh, bh, ao);

    gemm_out<<<dim3(MM/128, DD/128), 256, GEMM_SMEM>>>(ao, wo, bo, out);
}